// round 1
// baseline (speedup 1.0000x reference)
#include <cuda_runtime.h>
#include <cuda_bf16.h>

// Problem constants (fixed by dataset): B=2, C=256, N=4096
#define NB 2
#define NC 256
#define NP 4096

// ---------------- scratch (static device globals; no allocations) ----------
__device__ __nv_bfloat16 g_K[(size_t)NB * NP * NP];       // 64 MB affinity kernel, bf16
__device__ float g_a[NB * NP];
__device__ float g_b[NB * NP];
__device__ float g_KTa[NB * NP];
__device__ float g_invn1[NB * NP], g_invn2[NB * NP];
__device__ float g_sq1[NB * NP], g_sq2[NB * NP];
__device__ float g_eps, g_power;

// ---------------- scalar prep ----------------------------------------------
__global__ void fm_prep(const float* __restrict__ gamma, const float* __restrict__ epsilon) {
    if (threadIdx.x == 0) {
        float eps = expf(epsilon[0]) + 0.03f;
        float gam = expf(gamma[0]) + 0.03f;
        g_eps = eps;
        g_power = gam / (gam + eps);
    }
}

// ---------------- per-point prep: feature inv-norms, |p|^2, a0, zero KTa ---
__global__ void fm_point_prep(const float* __restrict__ pc1, const float* __restrict__ pc2,
                              const float* __restrict__ f1, const float* __restrict__ f2) {
    int p = blockIdx.x * blockDim.x + threadIdx.x;     // 0 .. NB*NP-1
    if (p >= NB * NP) return;
    int b = p >> 12;
    int n = p & (NP - 1);
    const float* F1 = f1 + (size_t)b * NC * NP + n;
    const float* F2 = f2 + (size_t)b * NC * NP + n;
    float s1 = 0.f, s2 = 0.f;
#pragma unroll 8
    for (int c = 0; c < NC; c++) {
        float v = F1[(size_t)c * NP]; s1 += v * v;
        float w = F2[(size_t)c * NP]; s2 += w * w;
    }
    g_invn1[p] = 1.0f / sqrtf(s1 + 1e-6f);
    g_invn2[p] = 1.0f / sqrtf(s2 + 1e-6f);
    const float* P1 = pc1 + (size_t)b * 3 * NP + n;
    const float* P2 = pc2 + (size_t)b * 3 * NP + n;
    float q1 = 0.f, q2 = 0.f;
#pragma unroll
    for (int d = 0; d < 3; d++) {
        float v = P1[(size_t)d * NP]; q1 += v * v;
        float w = P2[(size_t)d * NP]; q2 += w * w;
    }
    g_sq1[p] = q1;
    g_sq2[p] = q2;
    g_a[p]   = 1.0f / NP;
    g_KTa[p] = 0.0f;
}

// ---------------- K build: tiled GEMM + support/exp epilogue ---------------
// tile 128x128, 256 threads (16x16), 8x8 micro-tile (strided by 16),
// packed f32x2 FMA for 2x fp32 throughput.
__global__ __launch_bounds__(256, 2)
void fm_build_k(const float* __restrict__ f1, const float* __restrict__ f2,
                const float* __restrict__ pc1, const float* __restrict__ pc2) {
    __shared__ float As[16][128];
    __shared__ float Bs[16][128];
    __shared__ float sInv1[128], sInv2[128], sSq1[128], sSq2[128];
    __shared__ float sP1[3][128], sP2[3][128];

    int b  = blockIdx.z;
    int i0 = blockIdx.y * 128;
    int j0 = blockIdx.x * 128;
    int tid = threadIdx.x;
    int tx = tid & 15, ty = tid >> 4;

    if (tid < 128) {
        int i = i0 + tid, j = j0 + tid;
        sInv1[tid] = g_invn1[b * NP + i];
        sSq1[tid]  = g_sq1[b * NP + i];
        sInv2[tid] = g_invn2[b * NP + j];
        sSq2[tid]  = g_sq2[b * NP + j];
#pragma unroll
        for (int d = 0; d < 3; d++) {
            sP1[d][tid] = pc1[((size_t)b * 3 + d) * NP + i];
            sP2[d][tid] = pc2[((size_t)b * 3 + d) * NP + j];
        }
    }

    const float* F1 = f1 + (size_t)b * NC * NP;
    const float* F2 = f2 + (size_t)b * NC * NP;

    unsigned long long acc[8][4];
#pragma unroll
    for (int y = 0; y < 8; y++)
#pragma unroll
        for (int x = 0; x < 4; x++) acc[y][x] = 0ULL;

    for (int k0 = 0; k0 < NC; k0 += 16) {
        __syncthreads();
#pragma unroll
        for (int l = 0; l < 2; l++) {
            int idx = tid + l * 256;           // float4 index 0..511
            int kk  = idx >> 5;
            int ii4 = (idx & 31) << 2;
            *(float4*)&As[kk][ii4] = *(const float4*)&F1[(size_t)(k0 + kk) * NP + i0 + ii4];
            *(float4*)&Bs[kk][ii4] = *(const float4*)&F2[(size_t)(k0 + kk) * NP + j0 + ii4];
        }
        __syncthreads();
#pragma unroll
        for (int kk = 0; kk < 16; kk++) {
            float ar[8], br[8];
#pragma unroll
            for (int y = 0; y < 8; y++) ar[y] = As[kk][ty + y * 16];
#pragma unroll
            for (int x = 0; x < 8; x++) br[x] = Bs[kk][tx + x * 16];
            unsigned long long bp[4];
#pragma unroll
            for (int x = 0; x < 4; x++) {
                asm("mov.b64 %0, {%1,%2};" : "=l"(bp[x]) : "f"(br[2 * x]), "f"(br[2 * x + 1]));
            }
#pragma unroll
            for (int y = 0; y < 8; y++) {
                unsigned long long ap;
                asm("mov.b64 %0, {%1,%2};" : "=l"(ap) : "f"(ar[y]), "f"(ar[y]));
#pragma unroll
                for (int x = 0; x < 4; x++) {
                    asm("fma.rn.f32x2 %0, %1, %2, %3;"
                        : "=l"(acc[y][x]) : "l"(ap), "l"(bp[x]), "l"(acc[y][x]));
                }
            }
        }
    }

    float einv = 1.0f / g_eps;
    __nv_bfloat16* Kout = g_K + (size_t)b * NP * NP;
#pragma unroll
    for (int y = 0; y < 8; y++) {
        int ii = ty + y * 16;
        int i  = i0 + ii;
        float inv1 = sInv1[ii], sq1 = sSq1[ii];
        float p1x = sP1[0][ii], p1y = sP1[1][ii], p1z = sP1[2][ii];
#pragma unroll
        for (int x = 0; x < 4; x++) {
            float c0, c1;
            asm("mov.b64 {%0,%1}, %2;" : "=f"(c0), "=f"(c1) : "l"(acc[y][x]));
#pragma unroll
            for (int h = 0; h < 2; h++) {
                int xx = 2 * x + h;
                int jj = tx + xx * 16;
                int j  = j0 + jj;
                float corr = (h ? c1 : c0) * inv1 * sInv2[jj];
                float dist = sq1 + sSq2[jj]
                           - 2.0f * (p1x * sP2[0][jj] + p1y * sP2[1][jj] + p1z * sP2[2][jj]);
                float kv = (dist < 0.25f) ? expf((corr - 1.0f) * einv) : 0.0f;
                Kout[(size_t)i * NP + j] = __float2bfloat16(kv);
            }
        }
    }
}

// ---------------- Sinkhorn: KTa = K^T a (column sweep, atomics) ------------
// grid (8 jblocks, 16 iblocks, NB), 256 threads; each thread 2 cols via bf16x2.
__global__ void fm_kta(void) {
    int b = blockIdx.z;
    int j = blockIdx.x * 512 + threadIdx.x * 2;
    int i0 = blockIdx.y * 256;
    const __nv_bfloat16* Kp = g_K + (size_t)b * NP * NP;
    const float* ap = g_a + b * NP;
    float acc0 = 0.f, acc1 = 0.f;
#pragma unroll 8
    for (int i = i0; i < i0 + 256; i++) {
        __nv_bfloat162 kv = *(const __nv_bfloat162*)&Kp[(size_t)i * NP + j];
        float av = __ldg(&ap[i]);
        acc0 += __bfloat162float(kv.x) * av;
        acc1 += __bfloat162float(kv.y) * av;
    }
    atomicAdd(&g_KTa[b * NP + j],     acc0);
    atomicAdd(&g_KTa[b * NP + j + 1], acc1);
}

// ---------------- b = (prob2/(KTa+1e-8))^power; re-zero KTa ----------------
__global__ void fm_b_update(void) {
    int p = blockIdx.x * blockDim.x + threadIdx.x;
    if (p >= NB * NP) return;
    float kta = g_KTa[p];
    g_b[p] = powf((1.0f / NP) / (kta + 1e-8f), g_power);
    g_KTa[p] = 0.0f;
}

// ---------------- Kb (row sweep) fused with a-update -----------------------
__global__ void fm_kb_a(void) {
    int warp = (blockIdx.x * blockDim.x + threadIdx.x) >> 5;
    int lane = threadIdx.x & 31;
    if (warp >= NB * NP) return;
    int b = warp >> 12, i = warp & (NP - 1);
    const __nv_bfloat16* Krow = g_K + (size_t)b * NP * NP + (size_t)i * NP;
    const float* bp = g_b + b * NP;
    float acc = 0.f;
    for (int j = lane * 2; j < NP; j += 64) {
        __nv_bfloat162 kv = *(const __nv_bfloat162*)&Krow[j];
        float2 bv = *(const float2*)&bp[j];
        acc += __bfloat162float(kv.x) * bv.x + __bfloat162float(kv.y) * bv.y;
    }
#pragma unroll
    for (int o = 16; o; o >>= 1) acc += __shfl_xor_sync(0xffffffffu, acc, o);
    if (lane == 0)
        g_a[warp] = powf((1.0f / NP) / (acc + 1e-8f), g_power);
}

// ---------------- final: flow = (T p2)/(rowsum+1e-6) - p1 ------------------
__global__ void fm_flow(const float* __restrict__ pc1, const float* __restrict__ pc2,
                        float* __restrict__ out) {
    int warp = (blockIdx.x * blockDim.x + threadIdx.x) >> 5;
    int lane = threadIdx.x & 31;
    if (warp >= NB * NP) return;
    int b = warp >> 12, i = warp & (NP - 1);
    const __nv_bfloat16* Krow = g_K + (size_t)b * NP * NP + (size_t)i * NP;
    const float* bp  = g_b + b * NP;
    const float* p2x = pc2 + (size_t)b * 3 * NP;
    const float* p2y = p2x + NP;
    const float* p2z = p2y + NP;
    float s = 0.f, vx = 0.f, vy = 0.f, vz = 0.f;
    for (int j = lane * 2; j < NP; j += 64) {
        __nv_bfloat162 kv = *(const __nv_bfloat162*)&Krow[j];
        float2 bv = *(const float2*)&bp[j];
        float t0 = __bfloat162float(kv.x) * bv.x;
        float t1 = __bfloat162float(kv.y) * bv.y;
        s  += t0 + t1;
        vx += t0 * p2x[j] + t1 * p2x[j + 1];
        vy += t0 * p2y[j] + t1 * p2y[j + 1];
        vz += t0 * p2z[j] + t1 * p2z[j + 1];
    }
#pragma unroll
    for (int o = 16; o; o >>= 1) {
        s  += __shfl_xor_sync(0xffffffffu, s,  o);
        vx += __shfl_xor_sync(0xffffffffu, vx, o);
        vy += __shfl_xor_sync(0xffffffffu, vy, o);
        vz += __shfl_xor_sync(0xffffffffu, vz, o);
    }
    if (lane == 0) {
        float a = g_a[warp];
        float denom = a * s + 1e-6f;
        float rden = 1.0f / denom;
        const float* P1 = pc1 + (size_t)b * 3 * NP + i;
        out[warp * 3 + 0] = a * vx * rden - P1[0 * NP];
        out[warp * 3 + 1] = a * vy * rden - P1[1 * NP];
        out[warp * 3 + 2] = a * vz * rden - P1[2 * NP];
    }
}

// ---------------- launch ----------------------------------------------------
extern "C" void kernel_launch(void* const* d_in, const int* in_sizes, int n_in,
                              void* d_out, int out_size) {
    const float* pc1   = (const float*)d_in[0];
    const float* pc2   = (const float*)d_in[1];
    const float* f1    = (const float*)d_in[2];
    const float* f2    = (const float*)d_in[3];
    const float* gamma = (const float*)d_in[4];
    const float* eps   = (const float*)d_in[5];
    float* out = (float*)d_out;

    fm_prep<<<1, 32>>>(gamma, eps);
    fm_point_prep<<<(NB * NP + 255) / 256, 256>>>(pc1, pc2, f1, f2);
    fm_build_k<<<dim3(NP / 128, NP / 128, NB), 256>>>(f1, f2, pc1, pc2);
    for (int it = 0; it < 10; it++) {
        fm_kta<<<dim3(8, 16, NB), 256>>>();
        fm_b_update<<<(NB * NP + 255) / 256, 256>>>();
        fm_kb_a<<<NB * NP / 8, 256>>>();
    }
    fm_flow<<<NB * NP / 8, 256>>>(pc1, pc2, out);
}